// round 4
// baseline (speedup 1.0000x reference)
#include <cuda_runtime.h>

#define DEV __device__ __forceinline__

namespace {

constexpr int NB   = 8192;
constexpr int TT   = 200;
constexpr int EPC  = 56;    // elements per CTA (8 lanes each)
constexpr int NTHR = 448;
constexpr int ESTR = 152;   // per-element scratch stride (mod 32 == 24 -> conflict-free groups)
constexpr int S_HC = 0, S_XA = 64, S_SV = 128, S_EV = 144;
constexpr int WB   = EPC * ESTR;   // 8512 floats

// ---- encoder weight union (at WB) ----
constexpr int E_WI  = WB;                  // 192 x 8  (stride 12)
constexpr int E_WH  = E_WI + 192 * 12;     // 192 x 64 (stride 68)
constexpr int E_BRZ = E_WH + 192 * 68;     // 128 (bi+bh for r,z)
constexpr int E_BIN = E_BRZ + 128;         // 64
constexpr int E_BHN = E_BIN + 64;          // 64

// ---- rollout weight union (at WB) ----
constexpr int C_WI  = WB;                  // 192 x 32 (stride 36)
constexpr int C_WH  = C_WI + 192 * 36;     // 192 x 64 (stride 68)
constexpr int C_BRZ = C_WH + 192 * 68;     // 128
constexpr int C_BIN = C_BRZ + 128;         // 64
constexpr int C_BHN = C_BIN + 64;          // 64
constexpr int M0W   = C_BHN + 64;          // mlp_W0 64 x 72 (stride 76)
constexpr int M0B   = M0W + 64 * 76;       // 64
constexpr int M1W   = M0B + 64;            // mlp_W1 16 x 64 (stride 68)
constexpr int M1B   = M1W + 16 * 68;       // 16
constexpr int P0W   = M1B + 16;            // mc_W0 64 x 80 (stride 84)
constexpr int P0B   = P0W + 64 * 84;       // 64
constexpr int LNG   = P0B + 64;            // 3 x 64
constexpr int LNB   = LNG + 192;           // 3 x 64
constexpr int PW    = LNB + 192;           // mc_W 3 x 64 x 64 (stride 68)
constexpr int PB    = PW + 3 * 64 * 68;    // 192
constexpr int WOW   = PB + 192;            // mc_Wout 4 x 64 (stride 68)
constexpr int WOB   = WOW + 4 * 68;        // 4 (+4 pad)
constexpr int AM    = WOB + 8;             // sys_A 16 x 16 (stride 20)
constexpr int BM    = AM + 16 * 20;        // sys_B 16 x 4
constexpr int CMo   = BM + 64;             // sys_C 8 x 16 (stride 20)
constexpr int SMF   = CMo + 8 * 20;        // 54664 floats
constexpr size_t SMEMB = (size_t)SMF * sizeof(float);  // 218,656 B

// output layout: concat(obs_hat[B,200,8], commands[B,199,4], states[B,200,16])
constexpr size_t OFF_OH  = 0;
constexpr size_t OFF_CMD = (size_t)NB * 200 * 8;
constexpr size_t OFF_ST  = OFF_CMD + (size_t)NB * 199 * 4;

DEV float sigm(float v)   { return __fdividef(1.0f, 1.0f + __expf(-v)); }
DEV float tanh_f(float v) { return 1.0f - __fdividef(2.0f, 1.0f + __expf(2.0f * v)); }

// dot of register vector (4*C4 long) with shared row
template <int C4>
DEV float dotr(const float* x, const float* w) {
    float4 a = make_float4(0.f, 0.f, 0.f, 0.f);
#pragma unroll
    for (int c = 0; c < C4; c++) {
        float4 wv = *(const float4*)(w + 4 * c);
        a.x = fmaf(x[4 * c + 0], wv.x, a.x);
        a.y = fmaf(x[4 * c + 1], wv.y, a.y);
        a.z = fmaf(x[4 * c + 2], wv.z, a.z);
        a.w = fmaf(x[4 * c + 3], wv.w, a.w);
    }
    return (a.x + a.y) + (a.z + a.w);
}

// h (shared, 64) dotted with three shared weight rows at once (shares h loads)
DEV void dot64h3(const float* hh, const float* w0, const float* w1, const float* w2,
                 float& a0, float& a1, float& a2) {
    float4 A = make_float4(0.f, 0.f, 0.f, 0.f);
    float4 Bv = A, Cv = A;
#pragma unroll 4
    for (int c = 0; c < 16; c++) {
        float4 hv = *(const float4*)(hh + 4 * c);
        float4 u  = *(const float4*)(w0 + 4 * c);
        float4 v  = *(const float4*)(w1 + 4 * c);
        float4 w  = *(const float4*)(w2 + 4 * c);
        A.x  = fmaf(hv.x, u.x, A.x);  A.y  = fmaf(hv.y, u.y, A.y);
        A.z  = fmaf(hv.z, u.z, A.z);  A.w  = fmaf(hv.w, u.w, A.w);
        Bv.x = fmaf(hv.x, v.x, Bv.x); Bv.y = fmaf(hv.y, v.y, Bv.y);
        Bv.z = fmaf(hv.z, v.z, Bv.z); Bv.w = fmaf(hv.w, v.w, Bv.w);
        Cv.x = fmaf(hv.x, w.x, Cv.x); Cv.y = fmaf(hv.y, w.y, Cv.y);
        Cv.z = fmaf(hv.z, w.z, Cv.z); Cv.w = fmaf(hv.w, w.w, Cv.w);
    }
    a0 += (A.x + A.y) + (A.z + A.w);
    a1 += (Bv.x + Bv.y) + (Bv.z + Bv.w);
    a2 += (Cv.x + Cv.y) + (Cv.z + Cv.w);
}

// single shared-x dot64 with shared weight row
DEV float dot64s(const float* hh, const float* w) {
    float4 A = make_float4(0.f, 0.f, 0.f, 0.f);
#pragma unroll 4
    for (int c = 0; c < 16; c++) {
        float4 hv = *(const float4*)(hh + 4 * c);
        float4 wv = *(const float4*)(w + 4 * c);
        A.x = fmaf(hv.x, wv.x, A.x);
        A.y = fmaf(hv.y, wv.y, A.y);
        A.z = fmaf(hv.z, wv.z, A.z);
        A.w = fmaf(hv.w, wv.w, A.w);
    }
    return (A.x + A.y) + (A.z + A.w);
}

template <int C4>
DEV void gath(float* d, const float* s) {
#pragma unroll
    for (int c = 0; c < C4; c++) {
        float4 v = *(const float4*)(s + 4 * c);
        d[4 * c + 0] = v.x; d[4 * c + 1] = v.y;
        d[4 * c + 2] = v.z; d[4 * c + 3] = v.w;
    }
}

DEV void cp_pad(float* dst, const float* __restrict__ src, int rows, int cols, int stride, int tid) {
    int tot = rows * cols;
    for (int i = tid; i < tot; i += NTHR) {
        int r = i / cols;
        int c = i - r * cols;
        dst[r * stride + c] = src[i];
    }
}

DEV void load8(float* x, const float* p) {
    float4 a = __ldg((const float4*)p);
    float4 c = __ldg((const float4*)p + 1);
    x[0] = a.x; x[1] = a.y; x[2] = a.z; x[3] = a.w;
    x[4] = c.x; x[5] = c.y; x[6] = c.z; x[7] = c.w;
}

} // namespace

__global__ void __launch_bounds__(NTHR, 1)
sysid_kernel(const float* __restrict__ obs,
             const float* __restrict__ sysA, const float* __restrict__ sysB_, const float* __restrict__ sysC,
             const float* __restrict__ rWi, const float* __restrict__ rWh,
             const float* __restrict__ rbi, const float* __restrict__ rbh,
             const float* __restrict__ cWi, const float* __restrict__ cWh,
             const float* __restrict__ cbi, const float* __restrict__ cbh,
             const float* __restrict__ mW0, const float* __restrict__ mb0,
             const float* __restrict__ mW1, const float* __restrict__ mb1,
             const float* __restrict__ pW0, const float* __restrict__ pb0,
             const float* __restrict__ lg, const float* __restrict__ lb,
             const float* __restrict__ pW, const float* __restrict__ pb,
             const float* __restrict__ wo, const float* __restrict__ wob,
             float* __restrict__ out)
{
    extern __shared__ float sm[];
    const int tid = threadIdx.x, el = tid >> 3, sub = tid & 7;
    const int b = blockIdx.x * EPC + el;
    const bool act = (b < NB);
    const int beff = act ? b : (NB - 1);
    const float* ob = obs + (size_t)beff * (TT * 8);

    float* scr = sm + el * ESTR;
    float* hc = scr + S_HC;   // 64: GRU hidden (shared per element)
    float* xa = scr + S_XA;   // 64: activation exchange
    float* sv = scr + S_SV;   // 16: state exchange
    float* ev = scr + S_EV;   //  8: error / cmd exchange

    // ================= phase 1: encoder weights =================
    cp_pad(sm + E_WI, rWi, 192, 8, 12, tid);
    cp_pad(sm + E_WH, rWh, 192, 64, 68, tid);
    for (int i = tid; i < 128; i += NTHR) sm[E_BRZ + i] = rbi[i] + rbh[i];
    for (int i = tid; i < 64; i += NTHR) { sm[E_BIN + i] = rbi[128 + i]; sm[E_BHN + i] = rbh[128 + i]; }
    __syncthreads();

#pragma unroll
    for (int jj = 0; jj < 8; jj++) hc[jj * 8 + sub] = 0.f;
    __syncwarp();

    // ================= encoder GRU: 200 steps =================
#pragma unroll 1
    for (int t = 0; t < TT; t++) {
        float x[8];
        load8(x, ob + t * 8);
        float nh[8];
#pragma unroll
        for (int jj = 0; jj < 8; jj++) {
            int j = jj * 8 + sub;
            float ar = sm[E_BRZ + j], az = sm[E_BRZ + 64 + j];
            float ai = sm[E_BIN + j], ah = sm[E_BHN + j];
            ar += dotr<2>(x, sm + E_WI + j * 12);
            az += dotr<2>(x, sm + E_WI + (64 + j) * 12);
            ai += dotr<2>(x, sm + E_WI + (128 + j) * 12);
            dot64h3(hc, sm + E_WH + j * 68, sm + E_WH + (64 + j) * 68, sm + E_WH + (128 + j) * 68,
                    ar, az, ah);
            float r = sigm(ar), z = sigm(az);
            float n = tanh_f(fmaf(r, ah, ai));
            nh[jj] = n + z * (hc[j] - n);
        }
        __syncwarp();
#pragma unroll
        for (int jj = 0; jj < 8; jj++) hc[jj * 8 + sub] = nh[jj];
        __syncwarp();
    }

    // ================= phase 2: rollout weights =================
    __syncthreads();
    cp_pad(sm + C_WI, cWi, 192, 32, 36, tid);
    cp_pad(sm + C_WH, cWh, 192, 64, 68, tid);
    for (int i = tid; i < 128; i += NTHR) sm[C_BRZ + i] = cbi[i] + cbh[i];
    for (int i = tid; i < 64; i += NTHR) { sm[C_BIN + i] = cbi[128 + i]; sm[C_BHN + i] = cbh[128 + i]; }
    cp_pad(sm + M0W, mW0, 64, 72, 76, tid);
    for (int i = tid; i < 64; i += NTHR) sm[M0B + i] = mb0[i];
    cp_pad(sm + M1W, mW1, 16, 64, 68, tid);
    for (int i = tid; i < 16; i += NTHR) sm[M1B + i] = mb1[i];
    cp_pad(sm + P0W, pW0, 64, 80, 84, tid);
    for (int i = tid; i < 64; i += NTHR) sm[P0B + i] = pb0[i];
    for (int i = tid; i < 192; i += NTHR) { sm[LNG + i] = lg[i]; sm[LNB + i] = lb[i]; sm[PB + i] = pb[i]; }
    cp_pad(sm + PW, pW, 192, 64, 68, tid);
    cp_pad(sm + WOW, wo, 4, 64, 68, tid);
    for (int i = tid; i < 4; i += NTHR) sm[WOB + i] = wob[i];
    cp_pad(sm + AM, sysA, 16, 16, 20, tid);
    for (int i = tid; i < 64; i += NTHR) sm[BM + i] = sysB_[i];
    cp_pad(sm + CMo, sysC, 8, 16, 20, tid);
    __syncthreads();

    const size_t ob_oh = OFF_OH + (size_t)beff * 1600;
    const size_t ob_cm = OFF_CMD + (size_t)beff * 796;
    const size_t ob_st = OFF_ST + (size_t)beff * 3200;

    // ---- init MLP: x0 = tanh([hT, obs0] @ mlp_W0.T + b0); s0 = x0 @ mlp_W1.T + b1
    float x[8];
    load8(x, ob);
    float v0[8];
#pragma unroll
    for (int jj = 0; jj < 8; jj++) {
        int j = jj * 8 + sub;
        float a = sm[M0B + j] + dot64s(hc, sm + M0W + j * 76) + dotr<2>(x, sm + M0W + j * 76 + 64);
        v0[jj] = tanh_f(a);
    }
    __syncwarp();
#pragma unroll
    for (int jj = 0; jj < 8; jj++) xa[jj * 8 + sub] = v0[jj];
    __syncwarp();
    float x1[64];
    gath<16>(x1, xa);

    float s[16];
    {
        float t0 = sm[M1B + sub]     + dotr<16>(x1, sm + M1W + sub * 68);
        float t1 = sm[M1B + sub + 8] + dotr<16>(x1, sm + M1W + (sub + 8) * 68);
        sv[sub] = t0; sv[sub + 8] = t1;
        if (act) { out[ob_st + sub] = t0; out[ob_st + 8 + sub] = t1; }
        __syncwarp();
        gath<4>(s, sv);
        __syncwarp();
    }
    // hc := 0 for rollout GRU
#pragma unroll
    for (int jj = 0; jj < 8; jj++) hc[jj * 8 + sub] = 0.f;
    __syncwarp();

    // ================= rollout: 199 steps =================
#pragma unroll 1
    for (int t = 1; t < TT; t++) {
        load8(x, ob + t * 8);

        // obs_hat (for previous state) + error
        float oh = dotr<4>(s, sm + CMo + sub * 20);
        float ee = x[sub] - oh;
        ev[sub] = ee;
        if (act) out[ob_oh + (size_t)(t - 1) * 8 + sub] = oh;
        __syncwarp();
        float e[8];
        gath<2>(e, ev);

        // GRU cell: inpt = [s(16), x(8), e(8)]
        float nh[8];
#pragma unroll
        for (int jj = 0; jj < 8; jj++) {
            int j = jj * 8 + sub;
            const float* wr = sm + C_WI + j * 36;
            const float* wz = sm + C_WI + (64 + j) * 36;
            const float* wn = sm + C_WI + (128 + j) * 36;
            float ar = sm[C_BRZ + j]      + dotr<4>(s, wr) + dotr<2>(x, wr + 16) + dotr<2>(e, wr + 24);
            float az = sm[C_BRZ + 64 + j] + dotr<4>(s, wz) + dotr<2>(x, wz + 16) + dotr<2>(e, wz + 24);
            float ai = sm[C_BIN + j]      + dotr<4>(s, wn) + dotr<2>(x, wn + 16) + dotr<2>(e, wn + 24);
            float ah = sm[C_BHN + j];
            dot64h3(hc, sm + C_WH + j * 68, sm + C_WH + (64 + j) * 68, sm + C_WH + (128 + j) * 68,
                    ar, az, ah);
            float r = sigm(ar), z = sigm(az);
            float n = tanh_f(fmaf(r, ah, ai));
            nh[jj] = n + z * (hc[j] - n);
        }
        __syncwarp();
#pragma unroll
        for (int jj = 0; jj < 8; jj++) hc[jj * 8 + sub] = nh[jj];
        __syncwarp();

        // controller W0: u = [hc(64), x(8), e(8)] -> relu
#pragma unroll
        for (int jj = 0; jj < 8; jj++) {
            int j = jj * 8 + sub;
            const float* w = sm + P0W + j * 84;
            float a = sm[P0B + j] + dot64s(hc, w) + dotr<2>(x, w + 64) + dotr<2>(e, w + 72);
            v0[jj] = fmaxf(a, 0.f);
        }
        __syncwarp();
#pragma unroll
        for (int jj = 0; jj < 8; jj++) xa[jj * 8 + sub] = v0[jj];
        __syncwarp();
        gath<16>(x1, xa);

        // 3 x (LayerNorm -> linear -> relu)
#pragma unroll 1
        for (int li = 0; li < 3; li++) {
            float p0 = 0.f, p1 = 0.f, p2 = 0.f, p3 = 0.f;
            float q0 = 0.f, q1 = 0.f, q2 = 0.f, q3 = 0.f;
#pragma unroll
            for (int k = 0; k < 64; k += 4) {
                p0 += x1[k];     p1 += x1[k + 1]; p2 += x1[k + 2]; p3 += x1[k + 3];
                q0 = fmaf(x1[k], x1[k], q0);         q1 = fmaf(x1[k + 1], x1[k + 1], q1);
                q2 = fmaf(x1[k + 2], x1[k + 2], q2); q3 = fmaf(x1[k + 3], x1[k + 3], q3);
            }
            float m  = ((p0 + p1) + (p2 + p3)) * (1.f / 64.f);
            float vv = fmaf(-m, m, ((q0 + q1) + (q2 + q3)) * (1.f / 64.f));
            float rs = rsqrtf(vv + 1e-5f);
            const float* gp = sm + LNG + li * 64;
            const float* bp = sm + LNB + li * 64;
#pragma unroll
            for (int k = 0; k < 64; k += 4) {
                float4 g4 = *(const float4*)(gp + k);
                float4 b4 = *(const float4*)(bp + k);
                x1[k]     = fmaf((x1[k]     - m) * rs, g4.x, b4.x);
                x1[k + 1] = fmaf((x1[k + 1] - m) * rs, g4.y, b4.y);
                x1[k + 2] = fmaf((x1[k + 2] - m) * rs, g4.z, b4.z);
                x1[k + 3] = fmaf((x1[k + 3] - m) * rs, g4.w, b4.w);
            }
#pragma unroll
            for (int jj = 0; jj < 8; jj++) {
                int j = jj * 8 + sub;
                float a = sm[PB + li * 64 + j] + dotr<16>(x1, sm + PW + (li * 64 + j) * 68);
                v0[jj] = fmaxf(a, 0.f);
            }
            __syncwarp();
#pragma unroll
            for (int jj = 0; jj < 8; jj++) xa[jj * 8 + sub] = v0[jj];
            __syncwarp();
            gath<16>(x1, xa);
        }

        // cmd = x1 @ Wout.T + bout  (4 rows; lanes compute sub&3, lanes 0-3 publish)
        float cacc = sm[WOB + (sub & 3)] + dotr<16>(x1, sm + WOW + (sub & 3) * 68);
        __syncwarp();
        if (sub < 4) {
            ev[sub] = cacc;
            if (act) out[ob_cm + (size_t)(t - 1) * 4 + sub] = cacc;
        }
        __syncwarp();
        float cmd[4];
        {
            float4 cv = *(const float4*)ev;
            cmd[0] = cv.x; cmd[1] = cv.y; cmd[2] = cv.z; cmd[3] = cv.w;
        }

        // ns = s @ A.T + cmd @ B.T, with (|ns|<100) mask
        float n0 = dotr<4>(s, sm + AM + sub * 20)       + dotr<1>(cmd, sm + BM + sub * 4);
        float n1 = dotr<4>(s, sm + AM + (sub + 8) * 20) + dotr<1>(cmd, sm + BM + (sub + 8) * 4);
        n0 = (n0 > -100.f && n0 < 100.f) ? n0 : 0.f;
        n1 = (n1 > -100.f && n1 < 100.f) ? n1 : 0.f;
        __syncwarp();
        sv[sub] = n0; sv[sub + 8] = n1;
        if (act) {
            out[ob_st + (size_t)t * 16 + sub]     = n0;
            out[ob_st + (size_t)t * 16 + 8 + sub] = n1;
        }
        __syncwarp();
        gath<4>(s, sv);
    }

    // final obs_hat[199] = states[199] @ C.T
    float ohf = dotr<4>(s, sm + CMo + sub * 20);
    if (act) out[ob_oh + (size_t)199 * 8 + sub] = ohf;
}

extern "C" void kernel_launch(void* const* d_in, const int* in_sizes, int n_in,
                              void* d_out, int out_size) {
    (void)in_sizes; (void)n_in; (void)out_size;
    const float* obs  = (const float*)d_in[0];
    const float* sysA = (const float*)d_in[1];
    const float* sysB = (const float*)d_in[2];
    const float* sysC = (const float*)d_in[3];
    const float* rWi  = (const float*)d_in[4];
    const float* rWh  = (const float*)d_in[5];
    const float* rbi  = (const float*)d_in[6];
    const float* rbh  = (const float*)d_in[7];
    const float* cWi  = (const float*)d_in[8];
    const float* cWh  = (const float*)d_in[9];
    const float* cbi  = (const float*)d_in[10];
    const float* cbh  = (const float*)d_in[11];
    const float* mW0  = (const float*)d_in[12];
    const float* mb0  = (const float*)d_in[13];
    const float* mW1  = (const float*)d_in[14];
    const float* mb1  = (const float*)d_in[15];
    const float* pW0  = (const float*)d_in[16];
    const float* pb0  = (const float*)d_in[17];
    const float* lg   = (const float*)d_in[18];
    const float* lb   = (const float*)d_in[19];
    const float* pW   = (const float*)d_in[20];
    const float* pb   = (const float*)d_in[21];
    const float* wo   = (const float*)d_in[22];
    const float* wob  = (const float*)d_in[23];
    float* out = (float*)d_out;

    cudaFuncSetAttribute(sysid_kernel, cudaFuncAttributeMaxDynamicSharedMemorySize, (int)SMEMB);
    int grid = (NB + EPC - 1) / EPC;  // 147
    sysid_kernel<<<grid, NTHR, SMEMB>>>(obs, sysA, sysB, sysC,
                                        rWi, rWh, rbi, rbh,
                                        cWi, cWh, cbi, cbh,
                                        mW0, mb0, mW1, mb1,
                                        pW0, pb0, lg, lb, pW, pb, wo, wob,
                                        out);
}

// round 5
// speedup vs baseline: 1.0004x; 1.0004x over previous
#include <cuda_runtime.h>

#define DEV __device__ __forceinline__

namespace {

constexpr int NB   = 8192;
constexpr int TT   = 200;
constexpr int EPC  = 56;    // elements per CTA (8 lanes each)
constexpr int NTHR = 448;
constexpr int ESTR = 152;   // per-element scratch stride (mod 32 == 24 -> conflict-free groups)
constexpr int S_HC = 0, S_XA = 64, S_SV = 128, S_EV = 144;
constexpr int WB   = EPC * ESTR;   // 8512 floats

// ---- encoder weight union (at WB) ----
constexpr int E_WI  = WB;                  // 192 x 8  (stride 12)
constexpr int E_WH  = E_WI + 192 * 12;     // 192 x 64 (stride 68)
constexpr int E_BRZ = E_WH + 192 * 68;     // 128 (bi+bh for r,z)
constexpr int E_BIN = E_BRZ + 128;         // 64
constexpr int E_BHN = E_BIN + 64;          // 64

// ---- rollout weight union (at WB) ----
constexpr int C_WI  = WB;                  // 192 x 32 (stride 36)
constexpr int C_WH  = C_WI + 192 * 36;     // 192 x 64 (stride 68)
constexpr int C_BRZ = C_WH + 192 * 68;     // 128
constexpr int C_BIN = C_BRZ + 128;         // 64
constexpr int C_BHN = C_BIN + 64;          // 64
constexpr int M0W   = C_BHN + 64;          // mlp_W0 64 x 72 (stride 76)
constexpr int M0B   = M0W + 64 * 76;       // 64
constexpr int M1W   = M0B + 64;            // mlp_W1 16 x 64 (stride 68)
constexpr int M1B   = M1W + 16 * 68;       // 16
constexpr int P0W   = M1B + 16;            // mc_W0 64 x 80 (stride 84)
constexpr int P0B   = P0W + 64 * 84;       // 64
constexpr int LNG   = P0B + 64;            // 3 x 64
constexpr int LNB   = LNG + 192;           // 3 x 64
constexpr int PW    = LNB + 192;           // mc_W 3 x 64 x 64 (stride 68)
constexpr int PB    = PW + 3 * 64 * 68;    // 192
constexpr int WOW   = PB + 192;            // mc_Wout 4 x 64 (stride 68)
constexpr int WOB   = WOW + 4 * 68;        // 4 (+4 pad)
constexpr int AM    = WOB + 8;             // sys_A 16 x 16 (stride 20)
constexpr int BM    = AM + 16 * 20;        // sys_B 16 x 4
constexpr int CMo   = BM + 64;             // sys_C 8 x 16 (stride 20)
constexpr int SMF   = CMo + 8 * 20;        // 54664 floats
constexpr size_t SMEMB = (size_t)SMF * sizeof(float);  // 218,656 B

// output layout: concat(obs_hat[B,200,8], commands[B,199,4], states[B,200,16])
constexpr size_t OFF_OH  = 0;
constexpr size_t OFF_CMD = (size_t)NB * 200 * 8;
constexpr size_t OFF_ST  = OFF_CMD + (size_t)NB * 199 * 4;

DEV float sigm(float v)   { return __fdividef(1.0f, 1.0f + __expf(-v)); }
DEV float tanh_f(float v) { return 1.0f - __fdividef(2.0f, 1.0f + __expf(2.0f * v)); }

// dot of register vector (4*C4 long) with shared row
template <int C4>
DEV float dotr(const float* x, const float* w) {
    float4 a = make_float4(0.f, 0.f, 0.f, 0.f);
#pragma unroll
    for (int c = 0; c < C4; c++) {
        float4 wv = *(const float4*)(w + 4 * c);
        a.x = fmaf(x[4 * c + 0], wv.x, a.x);
        a.y = fmaf(x[4 * c + 1], wv.y, a.y);
        a.z = fmaf(x[4 * c + 2], wv.z, a.z);
        a.w = fmaf(x[4 * c + 3], wv.w, a.w);
    }
    return (a.x + a.y) + (a.z + a.w);
}

// h (shared, 64) dotted with three shared weight rows at once (shares h loads)
DEV void dot64h3(const float* hh, const float* w0, const float* w1, const float* w2,
                 float& a0, float& a1, float& a2) {
    float4 A = make_float4(0.f, 0.f, 0.f, 0.f);
    float4 Bv = A, Cv = A;
#pragma unroll 4
    for (int c = 0; c < 16; c++) {
        float4 hv = *(const float4*)(hh + 4 * c);
        float4 u  = *(const float4*)(w0 + 4 * c);
        float4 v  = *(const float4*)(w1 + 4 * c);
        float4 w  = *(const float4*)(w2 + 4 * c);
        A.x  = fmaf(hv.x, u.x, A.x);  A.y  = fmaf(hv.y, u.y, A.y);
        A.z  = fmaf(hv.z, u.z, A.z);  A.w  = fmaf(hv.w, u.w, A.w);
        Bv.x = fmaf(hv.x, v.x, Bv.x); Bv.y = fmaf(hv.y, v.y, Bv.y);
        Bv.z = fmaf(hv.z, v.z, Bv.z); Bv.w = fmaf(hv.w, v.w, Bv.w);
        Cv.x = fmaf(hv.x, w.x, Cv.x); Cv.y = fmaf(hv.y, w.y, Cv.y);
        Cv.z = fmaf(hv.z, w.z, Cv.z); Cv.w = fmaf(hv.w, w.w, Cv.w);
    }
    a0 += (A.x + A.y) + (A.z + A.w);
    a1 += (Bv.x + Bv.y) + (Bv.z + Bv.w);
    a2 += (Cv.x + Cv.y) + (Cv.z + Cv.w);
}

// single shared-x dot64 with shared weight row
DEV float dot64s(const float* hh, const float* w) {
    float4 A = make_float4(0.f, 0.f, 0.f, 0.f);
#pragma unroll 4
    for (int c = 0; c < 16; c++) {
        float4 hv = *(const float4*)(hh + 4 * c);
        float4 wv = *(const float4*)(w + 4 * c);
        A.x = fmaf(hv.x, wv.x, A.x);
        A.y = fmaf(hv.y, wv.y, A.y);
        A.z = fmaf(hv.z, wv.z, A.z);
        A.w = fmaf(hv.w, wv.w, A.w);
    }
    return (A.x + A.y) + (A.z + A.w);
}

template <int C4>
DEV void gath(float* d, const float* s) {
#pragma unroll
    for (int c = 0; c < C4; c++) {
        float4 v = *(const float4*)(s + 4 * c);
        d[4 * c + 0] = v.x; d[4 * c + 1] = v.y;
        d[4 * c + 2] = v.z; d[4 * c + 3] = v.w;
    }
}

DEV void cp_pad(float* dst, const float* __restrict__ src, int rows, int cols, int stride, int tid) {
    int tot = rows * cols;
    for (int i = tid; i < tot; i += NTHR) {
        int r = i / cols;
        int c = i - r * cols;
        dst[r * stride + c] = src[i];
    }
}

DEV void load8(float* x, const float* p) {
    float4 a = __ldg((const float4*)p);
    float4 c = __ldg((const float4*)p + 1);
    x[0] = a.x; x[1] = a.y; x[2] = a.z; x[3] = a.w;
    x[4] = c.x; x[5] = c.y; x[6] = c.z; x[7] = c.w;
}

} // namespace

__global__ void __launch_bounds__(NTHR, 1)
sysid_kernel(const float* __restrict__ obs,
             const float* __restrict__ sysA, const float* __restrict__ sysB_, const float* __restrict__ sysC,
             const float* __restrict__ rWi, const float* __restrict__ rWh,
             const float* __restrict__ rbi, const float* __restrict__ rbh,
             const float* __restrict__ cWi, const float* __restrict__ cWh,
             const float* __restrict__ cbi, const float* __restrict__ cbh,
             const float* __restrict__ mW0, const float* __restrict__ mb0,
             const float* __restrict__ mW1, const float* __restrict__ mb1,
             const float* __restrict__ pW0, const float* __restrict__ pb0,
             const float* __restrict__ lg, const float* __restrict__ lb,
             const float* __restrict__ pW, const float* __restrict__ pb,
             const float* __restrict__ wo, const float* __restrict__ wob,
             float* __restrict__ out)
{
    extern __shared__ float sm[];
    const int tid = threadIdx.x, el = tid >> 3, sub = tid & 7;
    const int b = blockIdx.x * EPC + el;
    const bool act = (b < NB);
    const int beff = act ? b : (NB - 1);
    const float* ob = obs + (size_t)beff * (TT * 8);

    float* scr = sm + el * ESTR;
    float* hc = scr + S_HC;   // 64: GRU hidden (shared per element)
    float* xa = scr + S_XA;   // 64: activation exchange
    float* sv = scr + S_SV;   // 16: state exchange
    float* ev = scr + S_EV;   //  8: error / cmd exchange

    // ================= phase 1: encoder weights =================
    cp_pad(sm + E_WI, rWi, 192, 8, 12, tid);
    cp_pad(sm + E_WH, rWh, 192, 64, 68, tid);
    for (int i = tid; i < 128; i += NTHR) sm[E_BRZ + i] = rbi[i] + rbh[i];
    for (int i = tid; i < 64; i += NTHR) { sm[E_BIN + i] = rbi[128 + i]; sm[E_BHN + i] = rbh[128 + i]; }
    __syncthreads();

#pragma unroll
    for (int jj = 0; jj < 8; jj++) hc[jj * 8 + sub] = 0.f;
    __syncwarp();

    // ================= encoder GRU: 200 steps =================
#pragma unroll 1
    for (int t = 0; t < TT; t++) {
        float x[8];
        load8(x, ob + t * 8);
        float nh[8];
#pragma unroll
        for (int jj = 0; jj < 8; jj++) {
            int j = jj * 8 + sub;
            float ar = sm[E_BRZ + j], az = sm[E_BRZ + 64 + j];
            float ai = sm[E_BIN + j], ah = sm[E_BHN + j];
            ar += dotr<2>(x, sm + E_WI + j * 12);
            az += dotr<2>(x, sm + E_WI + (64 + j) * 12);
            ai += dotr<2>(x, sm + E_WI + (128 + j) * 12);
            dot64h3(hc, sm + E_WH + j * 68, sm + E_WH + (64 + j) * 68, sm + E_WH + (128 + j) * 68,
                    ar, az, ah);
            float r = sigm(ar), z = sigm(az);
            float n = tanh_f(fmaf(r, ah, ai));
            nh[jj] = n + z * (hc[j] - n);
        }
        __syncwarp();
#pragma unroll
        for (int jj = 0; jj < 8; jj++) hc[jj * 8 + sub] = nh[jj];
        __syncwarp();
    }

    // ================= phase 2: rollout weights =================
    __syncthreads();
    cp_pad(sm + C_WI, cWi, 192, 32, 36, tid);
    cp_pad(sm + C_WH, cWh, 192, 64, 68, tid);
    for (int i = tid; i < 128; i += NTHR) sm[C_BRZ + i] = cbi[i] + cbh[i];
    for (int i = tid; i < 64; i += NTHR) { sm[C_BIN + i] = cbi[128 + i]; sm[C_BHN + i] = cbh[128 + i]; }
    cp_pad(sm + M0W, mW0, 64, 72, 76, tid);
    for (int i = tid; i < 64; i += NTHR) sm[M0B + i] = mb0[i];
    cp_pad(sm + M1W, mW1, 16, 64, 68, tid);
    for (int i = tid; i < 16; i += NTHR) sm[M1B + i] = mb1[i];
    cp_pad(sm + P0W, pW0, 64, 80, 84, tid);
    for (int i = tid; i < 64; i += NTHR) sm[P0B + i] = pb0[i];
    for (int i = tid; i < 192; i += NTHR) { sm[LNG + i] = lg[i]; sm[LNB + i] = lb[i]; sm[PB + i] = pb[i]; }
    cp_pad(sm + PW, pW, 192, 64, 68, tid);
    cp_pad(sm + WOW, wo, 4, 64, 68, tid);
    for (int i = tid; i < 4; i += NTHR) sm[WOB + i] = wob[i];
    cp_pad(sm + AM, sysA, 16, 16, 20, tid);
    for (int i = tid; i < 64; i += NTHR) sm[BM + i] = sysB_[i];
    cp_pad(sm + CMo, sysC, 8, 16, 20, tid);
    __syncthreads();

    const size_t ob_oh = OFF_OH + (size_t)beff * 1600;
    const size_t ob_cm = OFF_CMD + (size_t)beff * 796;
    const size_t ob_st = OFF_ST + (size_t)beff * 3200;

    // ---- init MLP: x0 = tanh([hT, obs0] @ mlp_W0.T + b0); s0 = x0 @ mlp_W1.T + b1
    float x[8];
    load8(x, ob);
    float v0[8];
#pragma unroll
    for (int jj = 0; jj < 8; jj++) {
        int j = jj * 8 + sub;
        float a = sm[M0B + j] + dot64s(hc, sm + M0W + j * 76) + dotr<2>(x, sm + M0W + j * 76 + 64);
        v0[jj] = tanh_f(a);
    }
    __syncwarp();
#pragma unroll
    for (int jj = 0; jj < 8; jj++) xa[jj * 8 + sub] = v0[jj];
    __syncwarp();
    float x1[64];
    gath<16>(x1, xa);

    float s[16];
    {
        float t0 = sm[M1B + sub]     + dotr<16>(x1, sm + M1W + sub * 68);
        float t1 = sm[M1B + sub + 8] + dotr<16>(x1, sm + M1W + (sub + 8) * 68);
        sv[sub] = t0; sv[sub + 8] = t1;
        if (act) { out[ob_st + sub] = t0; out[ob_st + 8 + sub] = t1; }
        __syncwarp();
        gath<4>(s, sv);
        __syncwarp();
    }
    // hc := 0 for rollout GRU
#pragma unroll
    for (int jj = 0; jj < 8; jj++) hc[jj * 8 + sub] = 0.f;
    __syncwarp();

    // ================= rollout: 199 steps =================
#pragma unroll 1
    for (int t = 1; t < TT; t++) {
        load8(x, ob + t * 8);

        // obs_hat (for previous state) + error
        float oh = dotr<4>(s, sm + CMo + sub * 20);
        float ee = x[sub] - oh;
        ev[sub] = ee;
        if (act) out[ob_oh + (size_t)(t - 1) * 8 + sub] = oh;
        __syncwarp();
        float e[8];
        gath<2>(e, ev);

        // GRU cell: inpt = [s(16), x(8), e(8)]
        float nh[8];
#pragma unroll
        for (int jj = 0; jj < 8; jj++) {
            int j = jj * 8 + sub;
            const float* wr = sm + C_WI + j * 36;
            const float* wz = sm + C_WI + (64 + j) * 36;
            const float* wn = sm + C_WI + (128 + j) * 36;
            float ar = sm[C_BRZ + j]      + dotr<4>(s, wr) + dotr<2>(x, wr + 16) + dotr<2>(e, wr + 24);
            float az = sm[C_BRZ + 64 + j] + dotr<4>(s, wz) + dotr<2>(x, wz + 16) + dotr<2>(e, wz + 24);
            float ai = sm[C_BIN + j]      + dotr<4>(s, wn) + dotr<2>(x, wn + 16) + dotr<2>(e, wn + 24);
            float ah = sm[C_BHN + j];
            dot64h3(hc, sm + C_WH + j * 68, sm + C_WH + (64 + j) * 68, sm + C_WH + (128 + j) * 68,
                    ar, az, ah);
            float r = sigm(ar), z = sigm(az);
            float n = tanh_f(fmaf(r, ah, ai));
            nh[jj] = n + z * (hc[j] - n);
        }
        __syncwarp();
#pragma unroll
        for (int jj = 0; jj < 8; jj++) hc[jj * 8 + sub] = nh[jj];
        __syncwarp();

        // controller W0: u = [hc(64), x(8), e(8)] -> relu
#pragma unroll
        for (int jj = 0; jj < 8; jj++) {
            int j = jj * 8 + sub;
            const float* w = sm + P0W + j * 84;
            float a = sm[P0B + j] + dot64s(hc, w) + dotr<2>(x, w + 64) + dotr<2>(e, w + 72);
            v0[jj] = fmaxf(a, 0.f);
        }
        __syncwarp();
#pragma unroll
        for (int jj = 0; jj < 8; jj++) xa[jj * 8 + sub] = v0[jj];
        __syncwarp();
        gath<16>(x1, xa);

        // 3 x (LayerNorm -> linear -> relu)
#pragma unroll 1
        for (int li = 0; li < 3; li++) {
            float p0 = 0.f, p1 = 0.f, p2 = 0.f, p3 = 0.f;
            float q0 = 0.f, q1 = 0.f, q2 = 0.f, q3 = 0.f;
#pragma unroll
            for (int k = 0; k < 64; k += 4) {
                p0 += x1[k];     p1 += x1[k + 1]; p2 += x1[k + 2]; p3 += x1[k + 3];
                q0 = fmaf(x1[k], x1[k], q0);         q1 = fmaf(x1[k + 1], x1[k + 1], q1);
                q2 = fmaf(x1[k + 2], x1[k + 2], q2); q3 = fmaf(x1[k + 3], x1[k + 3], q3);
            }
            float m  = ((p0 + p1) + (p2 + p3)) * (1.f / 64.f);
            float vv = fmaf(-m, m, ((q0 + q1) + (q2 + q3)) * (1.f / 64.f));
            float rs = rsqrtf(vv + 1e-5f);
            const float* gp = sm + LNG + li * 64;
            const float* bp = sm + LNB + li * 64;
#pragma unroll
            for (int k = 0; k < 64; k += 4) {
                float4 g4 = *(const float4*)(gp + k);
                float4 b4 = *(const float4*)(bp + k);
                x1[k]     = fmaf((x1[k]     - m) * rs, g4.x, b4.x);
                x1[k + 1] = fmaf((x1[k + 1] - m) * rs, g4.y, b4.y);
                x1[k + 2] = fmaf((x1[k + 2] - m) * rs, g4.z, b4.z);
                x1[k + 3] = fmaf((x1[k + 3] - m) * rs, g4.w, b4.w);
            }
#pragma unroll
            for (int jj = 0; jj < 8; jj++) {
                int j = jj * 8 + sub;
                float a = sm[PB + li * 64 + j] + dotr<16>(x1, sm + PW + (li * 64 + j) * 68);
                v0[jj] = fmaxf(a, 0.f);
            }
            __syncwarp();
#pragma unroll
            for (int jj = 0; jj < 8; jj++) xa[jj * 8 + sub] = v0[jj];
            __syncwarp();
            gath<16>(x1, xa);
        }

        // cmd = x1 @ Wout.T + bout  (4 rows; lanes compute sub&3, lanes 0-3 publish)
        float cacc = sm[WOB + (sub & 3)] + dotr<16>(x1, sm + WOW + (sub & 3) * 68);
        __syncwarp();
        if (sub < 4) {
            ev[sub] = cacc;
            if (act) out[ob_cm + (size_t)(t - 1) * 4 + sub] = cacc;
        }
        __syncwarp();
        float cmd[4];
        {
            float4 cv = *(const float4*)ev;
            cmd[0] = cv.x; cmd[1] = cv.y; cmd[2] = cv.z; cmd[3] = cv.w;
        }

        // ns = s @ A.T + cmd @ B.T, with (|ns|<100) mask
        float n0 = dotr<4>(s, sm + AM + sub * 20)       + dotr<1>(cmd, sm + BM + sub * 4);
        float n1 = dotr<4>(s, sm + AM + (sub + 8) * 20) + dotr<1>(cmd, sm + BM + (sub + 8) * 4);
        n0 = (n0 > -100.f && n0 < 100.f) ? n0 : 0.f;
        n1 = (n1 > -100.f && n1 < 100.f) ? n1 : 0.f;
        __syncwarp();
        sv[sub] = n0; sv[sub + 8] = n1;
        if (act) {
            out[ob_st + (size_t)t * 16 + sub]     = n0;
            out[ob_st + (size_t)t * 16 + 8 + sub] = n1;
        }
        __syncwarp();
        gath<4>(s, sv);
    }

    // final obs_hat[199] = states[199] @ C.T
    float ohf = dotr<4>(s, sm + CMo + sub * 20);
    if (act) out[ob_oh + (size_t)199 * 8 + sub] = ohf;
}

extern "C" void kernel_launch(void* const* d_in, const int* in_sizes, int n_in,
                              void* d_out, int out_size) {
    (void)in_sizes; (void)n_in; (void)out_size;
    const float* obs  = (const float*)d_in[0];
    const float* sysA = (const float*)d_in[1];
    const float* sysB = (const float*)d_in[2];
    const float* sysC = (const float*)d_in[3];
    const float* rWi  = (const float*)d_in[4];
    const float* rWh  = (const float*)d_in[5];
    const float* rbi  = (const float*)d_in[6];
    const float* rbh  = (const float*)d_in[7];
    const float* cWi  = (const float*)d_in[8];
    const float* cWh  = (const float*)d_in[9];
    const float* cbi  = (const float*)d_in[10];
    const float* cbh  = (const float*)d_in[11];
    const float* mW0  = (const float*)d_in[12];
    const float* mb0  = (const float*)d_in[13];
    const float* mW1  = (const float*)d_in[14];
    const float* mb1  = (const float*)d_in[15];
    const float* pW0  = (const float*)d_in[16];
    const float* pb0  = (const float*)d_in[17];
    const float* lg   = (const float*)d_in[18];
    const float* lb   = (const float*)d_in[19];
    const float* pW   = (const float*)d_in[20];
    const float* pb   = (const float*)d_in[21];
    const float* wo   = (const float*)d_in[22];
    const float* wob  = (const float*)d_in[23];
    float* out = (float*)d_out;

    cudaFuncSetAttribute(sysid_kernel, cudaFuncAttributeMaxDynamicSharedMemorySize, (int)SMEMB);
    int grid = (NB + EPC - 1) / EPC;  // 147
    sysid_kernel<<<grid, NTHR, SMEMB>>>(obs, sysA, sysB, sysC,
                                        rWi, rWh, rbi, rbh,
                                        cWi, cWh, cbi, cbh,
                                        mW0, mb0, mW1, mb1,
                                        pW0, pb0, lg, lb, pW, pb, wo, wob,
                                        out);
}

// round 6
// speedup vs baseline: 2.5181x; 2.5170x over previous
#include <cuda_runtime.h>
#define DEV __device__ __forceinline__
namespace {
constexpr int NB=8192, NBT=64, NT=256, WS=200;
// shared layout (float offsets)
constexpr int O_H=0;                 // 64x68 hidden (k-major)
constexpr int O_A0=O_H+64*68;        // 64x68 act buf 0
constexpr int O_A1=O_A0+64*68;       // 64x68 act buf 1
constexpr int O_U=O_A1+64*68;        // 32x68: s(0..15) x(16..23) e(24..31)
constexpr int O_P=O_U+32*68;         // 2 x 16x68 stat partials
constexpr int O_MNR=O_P+2176;        // 128: mean, rstd
constexpr int O_CMD=O_MNR+128;       // 4x68
constexpr int O_W=O_CMD+272;
// encoder union
constexpr int E_WHT=O_W, E_WIT=E_WHT+64*WS, E_B=E_WIT+8*WS;
// rollout union
constexpr int C_WHT=O_W, C_WIT=C_WHT+64*WS, C_B=C_WIT+32*WS;
constexpr int W0H=C_B+256, W0XE=W0H+64*68, W0B=W0XE+16*68;
constexpr int PWt=W0B+64, PBo=PWt+3*64*68, LNGo=PBo+192, LNBo=LNGo+192;
constexpr int WOo=LNBo+192, WOBo=WOo+256, AMo=WOBo+8, BMo=AMo+256, CMs=BMo+64;
constexpr int SMF=CMs+128;
constexpr size_t SMEMB=(size_t)SMF*4;   // 228,448 B
constexpr size_t OFF_CMD=(size_t)NB*1600;
constexpr size_t OFF_ST=OFF_CMD+(size_t)NB*796;

DEV float sigm(float v){ return __fdividef(1.0f,1.0f+__expf(-v)); }
DEV float tanh_f(float v){ return 1.0f-__fdividef(2.0f,1.0f+__expf(2.0f*v)); }

DEV float2 f2fma(float2 a,float2 b,float2 c){
  float2 d;
  asm("{\n\t.reg .b64 ra,rb,rc;\n\t"
      "mov.b64 ra,{%2,%3};\n\tmov.b64 rb,{%4,%5};\n\tmov.b64 rc,{%6,%7};\n\t"
      "fma.rn.f32x2 rc,ra,rb,rc;\n\tmov.b64 {%0,%1},rc;\n\t}"
      : "=f"(d.x),"=f"(d.y)
      : "f"(a.x),"f"(a.y),"f"(b.x),"f"(b.y),"f"(c.x),"f"(c.y));
  return d;
}
DEV void z2(float2(&A)[4][2]){
#pragma unroll
  for(int c=0;c<4;c++){ A[c][0]=make_float2(0.f,0.f); A[c][1]=make_float2(0.f,0.f); }
}

// acc[c][p]: cols cg4+c, rows rg4+2p, rg4+2p+1. 3-gate GEMM on 192-row transposed image.
template<int NK>
DEV void gemm3(float2(&aR)[4][2],float2(&aZ)[4][2],float2(&aN)[4][2],
               const float* WT,const float* Xs,int rg4,int cg4){
#pragma unroll 4
  for(int k=0;k<NK;k++){
    float4 hv=*(const float4*)(Xs+k*68+cg4);
    float2 hd[4]={{hv.x,hv.x},{hv.y,hv.y},{hv.z,hv.z},{hv.w,hv.w}};
    const float* wr=WT+k*WS+rg4;
    float4 w0=*(const float4*)wr, w1=*(const float4*)(wr+64), w2=*(const float4*)(wr+128);
    float2 w0a={w0.x,w0.y},w0b={w0.z,w0.w},w1a={w1.x,w1.y},w1b={w1.z,w1.w},w2a={w2.x,w2.y},w2b={w2.z,w2.w};
#pragma unroll
    for(int c=0;c<4;c++){
      aR[c][0]=f2fma(w0a,hd[c],aR[c][0]); aR[c][1]=f2fma(w0b,hd[c],aR[c][1]);
      aZ[c][0]=f2fma(w1a,hd[c],aZ[c][0]); aZ[c][1]=f2fma(w1b,hd[c],aZ[c][1]);
      aN[c][0]=f2fma(w2a,hd[c],aN[c][0]); aN[c][1]=f2fma(w2b,hd[c],aN[c][1]);
    }
  }
}
template<int NK>
DEV void gemm1(float2(&A)[4][2],const float* WT,const float* Xs,int rg4,int cg4){
#pragma unroll 4
  for(int k=0;k<NK;k++){
    float4 hv=*(const float4*)(Xs+k*68+cg4);
    float2 hd[4]={{hv.x,hv.x},{hv.y,hv.y},{hv.z,hv.z},{hv.w,hv.w}};
    float4 w=*(const float4*)(WT+k*68+rg4);
    float2 wa={w.x,w.y},wb={w.z,w.w};
#pragma unroll
    for(int c=0;c<4;c++){ A[c][0]=f2fma(wa,hd[c],A[c][0]); A[c][1]=f2fma(wb,hd[c],A[c][1]); }
  }
}
DEV float gat(const float2(&A)[4][2],int c,int r){ return (r&1)?A[c][r>>1].y:A[c][r>>1].x; }

DEV void gru_post(const float* sm,int Bb,int rg4,int cg4,
    float2(&aR)[4][2],float2(&aZ)[4][2],float2(&aI)[4][2],float2(&aH)[4][2],float4(&hn)[4]){
  float br[4],bz[4],bi[4],bh[4];
  *(float4*)br=*(const float4*)(sm+Bb+rg4);     *(float4*)bz=*(const float4*)(sm+Bb+64+rg4);
  *(float4*)bi=*(const float4*)(sm+Bb+128+rg4); *(float4*)bh=*(const float4*)(sm+Bb+192+rg4);
  float hv[4][4];
#pragma unroll
  for(int r=0;r<4;r++){
    float4 ho4=*(const float4*)(sm+O_H+(rg4+r)*68+cg4);
    float ho[4]={ho4.x,ho4.y,ho4.z,ho4.w};
#pragma unroll
    for(int c=0;c<4;c++){
      float rr=sigm(gat(aR,c,r)+br[r]), zz=sigm(gat(aZ,c,r)+bz[r]);
      float nn=tanh_f(gat(aI,c,r)+bi[r]+rr*(gat(aH,c,r)+bh[r]));
      hv[r][c]=nn+zz*(ho[c]-nn);
    }
  }
#pragma unroll
  for(int r=0;r<4;r++) hn[r]=make_float4(hv[r][0],hv[r][1],hv[r][2],hv[r][3]);
}

DEV void epi(float2(&A)[4][2],const float* bias,float* Adst,float* sm,int rg4,int cg4,bool stats){
  float bv[4]; *(float4*)bv=*(const float4*)(bias+rg4);
  float vv[4][4];
#pragma unroll
  for(int r=0;r<4;r++)
#pragma unroll
    for(int c=0;c<4;c++) vv[r][c]=fmaxf(gat(A,c,r)+bv[r],0.f);
#pragma unroll
  for(int r=0;r<4;r++) *(float4*)(Adst+(rg4+r)*68+cg4)=make_float4(vv[r][0],vv[r][1],vv[r][2],vv[r][3]);
  if(stats){
    float s[4],q[4];
#pragma unroll
    for(int c=0;c<4;c++){
      s[c]=vv[0][c]+vv[1][c]+vv[2][c]+vv[3][c];
      q[c]=vv[0][c]*vv[0][c]+vv[1][c]*vv[1][c]+vv[2][c]*vv[2][c]+vv[3][c]*vv[3][c];
    }
    int rg=rg4>>2;
    *(float4*)(sm+O_P+rg*68+cg4)=make_float4(s[0],s[1],s[2],s[3]);
    *(float4*)(sm+O_P+1088+rg*68+cg4)=make_float4(q[0],q[1],q[2],q[3]);
  }
}
DEV void stage2(float* sm,int tid){
  if(tid<64){
    float s=0.f,q=0.f;
#pragma unroll
    for(int g=0;g<16;g++){ s+=sm[O_P+g*68+tid]; q+=sm[O_P+1088+g*68+tid]; }
    float m=s*(1.f/64.f), v=q*(1.f/64.f)-m*m;
    sm[O_MNR+tid]=m; sm[O_MNR+64+tid]=rsqrtf(v+1e-5f);
  }
}
DEV void normA(float* A,const float* sm,int li,int rg4,int cg4){
  float4 m4=*(const float4*)(sm+O_MNR+cg4), r4=*(const float4*)(sm+O_MNR+64+cg4);
#pragma unroll
  for(int r=0;r<4;r++){
    int fr=rg4+r;
    float g=sm[LNGo+li*64+fr], bb=sm[LNBo+li*64+fr];
    float4 v=*(float4*)(A+fr*68+cg4);
    v.x=(v.x-m4.x)*r4.x*g+bb; v.y=(v.y-m4.y)*r4.y*g+bb;
    v.z=(v.z-m4.z)*r4.z*g+bb; v.w=(v.w-m4.w)*r4.w*g+bb;
    *(float4*)(A+fr*68+cg4)=v;
  }
}
DEV void cpT(float* dst,const float* __restrict__ src,int R,int K,int ks,int tid){
  for(int i=tid;i<R*K;i+=NT){ int r=i/K,k=i-r*K; dst[k*ks+r]=src[i]; }
}
} // namespace

__global__ void __launch_bounds__(NT,1)
sysid_kernel(const float* __restrict__ obs,
             const float* __restrict__ sysA,const float* __restrict__ sysB_,const float* __restrict__ sysC,
             const float* __restrict__ rWi,const float* __restrict__ rWh,
             const float* __restrict__ rbi,const float* __restrict__ rbh,
             const float* __restrict__ cWi,const float* __restrict__ cWh,
             const float* __restrict__ cbi,const float* __restrict__ cbh,
             const float* __restrict__ mW0,const float* __restrict__ mb0,
             const float* __restrict__ mW1,const float* __restrict__ mb1,
             const float* __restrict__ pW0,const float* __restrict__ pb0,
             const float* __restrict__ lg,const float* __restrict__ lb,
             const float* __restrict__ pW,const float* __restrict__ pb,
             const float* __restrict__ wo,const float* __restrict__ wob,
             float* __restrict__ out)
{
  extern __shared__ float sm[];
  const int tid=threadIdx.x, lane=tid&31, warp=tid>>5;
  const int cg4=(lane&15)*4, rg4=(warp*2+(lane>>4))*4;
  const int b0=blockIdx.x*NBT;
  const int oc=tid>>3, oo=tid&7;   // obs loader mapping (2 per thread: cols oc, oc+32)
  float* A0=sm+O_A0; float* A1=sm+O_A1;

  // ---- encoder weights ----
  cpT(sm+E_WHT,rWh,192,64,WS,tid);
  cpT(sm+E_WIT,rWi,192,8,WS,tid);
  for(int i=tid;i<64;i+=NT){
    sm[E_B+i]=rbi[i]+rbh[i]; sm[E_B+64+i]=rbi[64+i]+rbh[64+i];
    sm[E_B+128+i]=rbi[128+i]; sm[E_B+192+i]=rbh[128+i];
  }
  for(int i=tid;i<64*68;i+=NT) sm[O_H+i]=0.f;
  sm[O_U+(16+oo)*68+oc]=obs[(size_t)(b0+oc)*1600+oo];
  sm[O_U+(16+oo)*68+oc+32]=obs[(size_t)(b0+oc+32)*1600+oo];
  __syncthreads();

  // ---- encoder GRU: 200 steps ----
#pragma unroll 1
  for(int t=0;t<200;t++){
    int tn=(t<199)?t+1:t;
    float p0=obs[(size_t)(b0+oc)*1600+tn*8+oo];
    float p1=obs[(size_t)(b0+oc+32)*1600+tn*8+oo];
    float2 aR[4][2],aZ[4][2],aI[4][2],aH[4][2];
    z2(aR);z2(aZ);z2(aI);z2(aH);
    gemm3<8>(aR,aZ,aI,sm+E_WIT,sm+O_U+16*68,rg4,cg4);
    gemm3<64>(aR,aZ,aH,sm+E_WHT,sm+O_H,rg4,cg4);
    float4 hn[4]; gru_post(sm,E_B,rg4,cg4,aR,aZ,aI,aH,hn);
    __syncthreads();
#pragma unroll
    for(int r=0;r<4;r++) *(float4*)(sm+O_H+(rg4+r)*68+cg4)=hn[r];
    sm[O_U+(16+oo)*68+oc]=p0; sm[O_U+(16+oo)*68+oc+32]=p1;
    __syncthreads();
  }

  // ---- init MLP: x0=tanh([hT,obs0]@mW0.T+b0); s0=x0@mW1.T+b1 ----
  cpT(sm+O_W,mW0,64,72,68,tid);
  sm[O_U+(16+oo)*68+oc]=obs[(size_t)(b0+oc)*1600+oo];
  sm[O_U+(16+oo)*68+oc+32]=obs[(size_t)(b0+oc+32)*1600+oo];
  __syncthreads();
  {
    float2 a[4][2]; z2(a);
    gemm1<64>(a,sm+O_W,sm+O_H,rg4,cg4);
    gemm1<8>(a,sm+O_W+64*68,sm+O_U+16*68,rg4,cg4);
#pragma unroll
    for(int r=0;r<4;r++){
      float bb=__ldg(mb0+rg4+r);
      float4 v=make_float4(tanh_f(gat(a,0,r)+bb),tanh_f(gat(a,1,r)+bb),
                           tanh_f(gat(a,2,r)+bb),tanh_f(gat(a,3,r)+bb));
      *(float4*)(A0+(rg4+r)*68+cg4)=v;
    }
  }
  __syncthreads();
  {
    int col=tid&63, rq=tid>>6;
#pragma unroll
    for(int i=0;i<4;i++){
      int r=rq*4+i;
      float acc=__ldg(mb1+r);
      for(int k=0;k<64;k++) acc=fmaf(A0[k*68+col],__ldg(mW1+r*64+k),acc);
      sm[O_U+r*68+col]=acc;
      out[OFF_ST+(size_t)(b0+col)*3200+r]=acc;
    }
    for(int i=tid;i<64*68;i+=NT) sm[O_H+i]=0.f;
    sm[O_U+(16+oo)*68+oc]=obs[(size_t)(b0+oc)*1600+8+oo];
    sm[O_U+(16+oo)*68+oc+32]=obs[(size_t)(b0+oc+32)*1600+8+oo];
  }
  __syncthreads();

  // ---- rollout weights ----
  cpT(sm+C_WHT,cWh,192,64,WS,tid);
  cpT(sm+C_WIT,cWi,192,32,WS,tid);
  for(int i=tid;i<64;i+=NT){
    sm[C_B+i]=cbi[i]+cbh[i]; sm[C_B+64+i]=cbi[64+i]+cbh[64+i];
    sm[C_B+128+i]=cbi[128+i]; sm[C_B+192+i]=cbh[128+i];
  }
  for(int i=tid;i<64*80;i+=NT){ int r=i/80,k=i-r*80;
    if(k<64) sm[W0H+k*68+r]=pW0[i]; else sm[W0XE+(k-64)*68+r]=pW0[i]; }
  for(int i=tid;i<64;i+=NT) sm[W0B+i]=pb0[i];
  for(int i=tid;i<12288;i+=NT){ int li=i>>12,rem=i&4095,r=rem>>6,k=rem&63;
    sm[PWt+li*4352+k*68+r]=pW[i]; }
  for(int i=tid;i<192;i+=NT){ sm[PBo+i]=pb[i]; sm[LNGo+i]=lg[i]; sm[LNBo+i]=lb[i]; }
  for(int i=tid;i<256;i+=NT){ sm[WOo+i]=wo[i]; sm[AMo+i]=sysA[i]; }
  if(tid<4) sm[WOBo+tid]=wob[tid];
  for(int i=tid;i<64;i+=NT) sm[BMo+i]=sysB_[i];
  for(int i=tid;i<128;i+=NT) sm[CMs+i]=sysC[i];
  __syncthreads();

  // ---- rollout: 199 steps ----
#pragma unroll 1
  for(int t=1;t<200;t++){
    int tn=(t<199)?t+1:t;
    float p0=obs[(size_t)(b0+oc)*1600+tn*8+oo];
    float p1=obs[(size_t)(b0+oc+32)*1600+tn*8+oo];

    // S1: oh = C@s ; e = x - oh ; emit obs_hat[t-1]
    if(tid<128){
      int row=tid>>4, c4=(tid&15)*4;
      float o[4]={0.f,0.f,0.f,0.f};
#pragma unroll
      for(int k=0;k<16;k++){
        float cw=sm[CMs+row*16+k];
        float4 sv=*(const float4*)(sm+O_U+k*68+c4);
        o[0]=fmaf(cw,sv.x,o[0]); o[1]=fmaf(cw,sv.y,o[1]);
        o[2]=fmaf(cw,sv.z,o[2]); o[3]=fmaf(cw,sv.w,o[3]);
      }
      float4 xv=*(const float4*)(sm+O_U+(16+row)*68+c4);
      *(float4*)(sm+O_U+(24+row)*68+c4)=make_float4(xv.x-o[0],xv.y-o[1],xv.z-o[2],xv.w-o[3]);
#pragma unroll
      for(int j=0;j<4;j++) out[(size_t)(b0+c4+j)*1600+(size_t)(t-1)*8+row]=o[j];
    }
    __syncthreads();

    // S2: GRU
    {
      float2 aR[4][2],aZ[4][2],aI[4][2],aH[4][2];
      z2(aR);z2(aZ);z2(aI);z2(aH);
      gemm3<32>(aR,aZ,aI,sm+C_WIT,sm+O_U,rg4,cg4);
      gemm3<64>(aR,aZ,aH,sm+C_WHT,sm+O_H,rg4,cg4);
      float4 hn[4]; gru_post(sm,C_B,rg4,cg4,aR,aZ,aI,aH,hn);
      __syncthreads();
#pragma unroll
      for(int r=0;r<4;r++) *(float4*)(sm+O_H+(rg4+r)*68+cg4)=hn[r];
    }
    __syncthreads();

    // S3: W0 + LN0
    {
      float2 a[4][2]; z2(a);
      gemm1<64>(a,sm+W0H,sm+O_H,rg4,cg4);
      gemm1<16>(a,sm+W0XE,sm+O_U+16*68,rg4,cg4);
      epi(a,sm+W0B,A0,sm,rg4,cg4,true);
    }
    __syncthreads();
    stage2(sm,tid);
    __syncthreads();
    normA(A0,sm,0,rg4,cg4);
    __syncthreads();

    // S4: 3 x (linear -> relu [-> LN])
    float* cur=A0; float* nxt=A1;
#pragma unroll 1
    for(int li=0;li<3;li++){
      float2 a[4][2]; z2(a);
      gemm1<64>(a,sm+PWt+li*4352,cur,rg4,cg4);
      epi(a,sm+PBo+li*64,nxt,sm,rg4,cg4,li<2);
      __syncthreads();
      if(li<2){ stage2(sm,tid); __syncthreads(); normA(nxt,sm,li+1,rg4,cg4); __syncthreads(); }
      float* tp=cur; cur=nxt; nxt=tp;
    }

    // S5: cmd = x@Wout.T + b ; emit commands[t-1]
    {
      int col=tid&63, r=tid>>6;
      float acc=sm[WOBo+r];
      for(int k=0;k<64;k++) acc=fmaf(cur[k*68+col],sm[WOo+r*64+k],acc);
      sm[O_CMD+r*68+col]=acc;
      out[OFF_CMD+(size_t)(b0+col)*796+(size_t)(t-1)*4+r]=acc;
    }
    __syncthreads();

    // S6: ns = s@A.T + cmd@B.T, mask, store states[t], advance
    {
      int col=tid&63, rq=tid>>6;
      float ns[4];
#pragma unroll
      for(int i=0;i<4;i++){
        int r=rq*4+i; float a=0.f;
#pragma unroll
        for(int k=0;k<16;k++) a=fmaf(sm[AMo+r*16+k],sm[O_U+k*68+col],a);
#pragma unroll
        for(int k=0;k<4;k++) a=fmaf(sm[BMo+r*4+k],sm[O_CMD+k*68+col],a);
        ns[i]=(a>-100.f&&a<100.f)?a:0.f;
      }
      __syncthreads();
#pragma unroll
      for(int i=0;i<4;i++){
        sm[O_U+(rq*4+i)*68+col]=ns[i];
        out[OFF_ST+(size_t)(b0+col)*3200+(size_t)t*16+rq*4+i]=ns[i];
      }
      sm[O_U+(16+oo)*68+oc]=p0; sm[O_U+(16+oo)*68+oc+32]=p1;
    }
    __syncthreads();
  }

  // final obs_hat[199] = states[199]@C.T
  if(tid<128){
    int row=tid>>4, c4=(tid&15)*4;
    float o[4]={0.f,0.f,0.f,0.f};
#pragma unroll
    for(int k=0;k<16;k++){
      float cw=sm[CMs+row*16+k];
      float4 sv=*(const float4*)(sm+O_U+k*68+c4);
      o[0]=fmaf(cw,sv.x,o[0]); o[1]=fmaf(cw,sv.y,o[1]);
      o[2]=fmaf(cw,sv.z,o[2]); o[3]=fmaf(cw,sv.w,o[3]);
    }
#pragma unroll
    for(int j=0;j<4;j++) out[(size_t)(b0+c4+j)*1600+1592+row]=o[j];
  }
}

extern "C" void kernel_launch(void* const* d_in, const int* in_sizes, int n_in,
                              void* d_out, int out_size) {
  (void)in_sizes;(void)n_in;(void)out_size;
  cudaFuncSetAttribute(sysid_kernel,cudaFuncAttributeMaxDynamicSharedMemorySize,(int)SMEMB);
  sysid_kernel<<<NB/NBT,NT,SMEMB>>>(
    (const float*)d_in[0],(const float*)d_in[1],(const float*)d_in[2],(const float*)d_in[3],
    (const float*)d_in[4],(const float*)d_in[5],(const float*)d_in[6],(const float*)d_in[7],
    (const float*)d_in[8],(const float*)d_in[9],(const float*)d_in[10],(const float*)d_in[11],
    (const float*)d_in[12],(const float*)d_in[13],(const float*)d_in[14],(const float*)d_in[15],
    (const float*)d_in[16],(const float*)d_in[17],(const float*)d_in[18],(const float*)d_in[19],
    (const float*)d_in[20],(const float*)d_in[21],(const float*)d_in[22],(const float*)d_in[23],
    (float*)d_out);
}

// round 8
// speedup vs baseline: 2.5549x; 1.0146x over previous
#include <cuda_runtime.h>
#define DEV __device__ __forceinline__
namespace {
constexpr int NB=8192, NBT=64, NT=256, WS=200;

// ---- activation region (union: encoder ping-pong vs rollout U/A0/A1) ----
constexpr int O_U  = 0;              // rollout: 96x68 (s:0-15, x:16-23, e:24-31, H:32-95)
constexpr int O_A0 = 96*68;          // 6528: 64x68
constexpr int O_A1 = O_A0+64*68;     // 10880: 64x68
constexpr int HXSZ = 72*68;          // encoder buf: H(0-63) + X(64-71)
constexpr int O_P  = O_A1+64*68;     // 15232: 2 x 8x68 stat partials
constexpr int O_MNR= O_P+2*8*68;     // 16320: mean(64), rstd(64)
constexpr int O_CMD= O_MNR+128;      // 16448: 4x68
constexpr int O_OHS= O_CMD+4*68;     // 16720: 8x68 obs_hat staging
constexpr int O_W  = O_OHS+8*68;     // 17264 weight union base
// encoder union
constexpr int E_W=O_W, E_B=E_W+72*WS;          // 72x200 image (k:0-63 Wh, 64-71 Wi), 256 bias
// rollout union
constexpr int C_W=O_W, C_B=C_W+96*WS;          // 96x200 image (k:0-31 Wi, 32-95 Wh), 256 bias
constexpr int W0H=C_B+256, W0XE=W0H+64*68, W0B=W0XE+16*68;
constexpr int PWt=W0B+64, PBo=PWt+3*64*68, LNGo=PBo+192, LNBo=LNGo+192;
constexpr int WOo=LNBo+192, WOBo=WOo+256, AMo=WOBo+8, BMo=AMo+256, CMs=BMo+64;
constexpr int SMF=CMs+128;
constexpr size_t SMEMB=(size_t)SMF*4;          // 226,272 B
constexpr size_t OFF_CMD=(size_t)NB*1600;
constexpr size_t OFF_ST =OFF_CMD+(size_t)NB*796;

DEV float sigm(float v){ return __fdividef(1.0f,1.0f+__expf(-v)); }
DEV float tanh_f(float v){ return 1.0f-__fdividef(2.0f,1.0f+__expf(2.0f*v)); }

DEV float2 f2fma(float2 a,float2 b,float2 c){
  float2 d;
  asm("{\n\t.reg .b64 ra,rb,rc;\n\t"
      "mov.b64 ra,{%2,%3};\n\tmov.b64 rb,{%4,%5};\n\tmov.b64 rc,{%6,%7};\n\t"
      "fma.rn.f32x2 rc,ra,rb,rc;\n\tmov.b64 {%0,%1},rc;\n\t}"
      : "=f"(d.x),"=f"(d.y)
      : "f"(a.x),"f"(a.y),"f"(b.x),"f"(b.y),"f"(c.x),"f"(c.y));
  return d;
}
DEV void z2(float2(&A)[4][2]){
#pragma unroll
  for(int c=0;c<4;c++){ A[c][0]=make_float2(0.f,0.f); A[c][1]=make_float2(0.f,0.f); }
}
template<int NK>
DEV void gemm3(float2(&aR)[4][2],float2(&aZ)[4][2],float2(&aN)[4][2],
               const float* WT,const float* Xs,int rg4,int cg4){
#pragma unroll 4
  for(int k=0;k<NK;k++){
    float4 hv=*(const float4*)(Xs+k*68+cg4);
    float2 hd[4]={{hv.x,hv.x},{hv.y,hv.y},{hv.z,hv.z},{hv.w,hv.w}};
    const float* wr=WT+k*WS+rg4;
    float4 w0=*(const float4*)wr, w1=*(const float4*)(wr+64), w2=*(const float4*)(wr+128);
    float2 w0a={w0.x,w0.y},w0b={w0.z,w0.w},w1a={w1.x,w1.y},w1b={w1.z,w1.w},w2a={w2.x,w2.y},w2b={w2.z,w2.w};
#pragma unroll
    for(int c=0;c<4;c++){
      aR[c][0]=f2fma(w0a,hd[c],aR[c][0]); aR[c][1]=f2fma(w0b,hd[c],aR[c][1]);
      aZ[c][0]=f2fma(w1a,hd[c],aZ[c][0]); aZ[c][1]=f2fma(w1b,hd[c],aZ[c][1]);
      aN[c][0]=f2fma(w2a,hd[c],aN[c][0]); aN[c][1]=f2fma(w2b,hd[c],aN[c][1]);
    }
  }
}
template<int NK>
DEV void gemm1(float2(&A)[4][2],const float* WT,const float* Xs,int rg4,int cg4){
#pragma unroll 4
  for(int k=0;k<NK;k++){
    float4 hv=*(const float4*)(Xs+k*68+cg4);
    float2 hd[4]={{hv.x,hv.x},{hv.y,hv.y},{hv.z,hv.z},{hv.w,hv.w}};
    float4 w=*(const float4*)(WT+k*68+rg4);
    float2 wa={w.x,w.y},wb={w.z,w.w};
#pragma unroll
    for(int c=0;c<4;c++){ A[c][0]=f2fma(wa,hd[c],A[c][0]); A[c][1]=f2fma(wb,hd[c],A[c][1]); }
  }
}
DEV float gat(const float2(&A)[4][2],int c,int r){ return (r&1)?A[c][r>>1].y:A[c][r>>1].x; }

DEV void gru_post(const float* sm,int Bb,const float* hb,int rg4,int cg4,
    float2(&aR)[4][2],float2(&aZ)[4][2],float2(&aI)[4][2],float2(&aH)[4][2],float4(&hn)[4]){
  float br[4],bz[4],bi[4],bh[4];
  *(float4*)br=*(const float4*)(sm+Bb+rg4);     *(float4*)bz=*(const float4*)(sm+Bb+64+rg4);
  *(float4*)bi=*(const float4*)(sm+Bb+128+rg4); *(float4*)bh=*(const float4*)(sm+Bb+192+rg4);
  float hv[4][4];
#pragma unroll
  for(int r=0;r<4;r++){
    float4 ho4=*(const float4*)(hb+(rg4+r)*68+cg4);
    float ho[4]={ho4.x,ho4.y,ho4.z,ho4.w};
#pragma unroll
    for(int c=0;c<4;c++){
      float rr=sigm(gat(aR,c,r)+br[r]), zz=sigm(gat(aZ,c,r)+bz[r]);
      float nn=tanh_f(gat(aI,c,r)+bi[r]+rr*(gat(aH,c,r)+bh[r]));
      hv[r][c]=nn+zz*(ho[c]-nn);
    }
  }
#pragma unroll
  for(int r=0;r<4;r++) hn[r]=make_float4(hv[r][0],hv[r][1],hv[r][2],hv[r][3]);
}

DEV void epi(float2(&A)[4][2],const float* bias,float* Adst,float* sm,
             int rg4,int cg4,int warp,int lane,bool stats){
  float bv[4]; *(float4*)bv=*(const float4*)(bias+rg4);
  float vv[4][4];
#pragma unroll
  for(int r=0;r<4;r++)
#pragma unroll
    for(int c=0;c<4;c++) vv[r][c]=fmaxf(gat(A,c,r)+bv[r],0.f);
#pragma unroll
  for(int r=0;r<4;r++) *(float4*)(Adst+(rg4+r)*68+cg4)=make_float4(vv[r][0],vv[r][1],vv[r][2],vv[r][3]);
  if(stats){
    float s[4],q[4];
#pragma unroll
    for(int c=0;c<4;c++){
      s[c]=vv[0][c]+vv[1][c]+vv[2][c]+vv[3][c];
      q[c]=vv[0][c]*vv[0][c]+vv[1][c]*vv[1][c]+vv[2][c]*vv[2][c]+vv[3][c]*vv[3][c];
      s[c]+=__shfl_xor_sync(0xffffffffu,s[c],16);
      q[c]+=__shfl_xor_sync(0xffffffffu,q[c],16);
    }
    if(lane<16){
      *(float4*)(sm+O_P+warp*68+cg4)=make_float4(s[0],s[1],s[2],s[3]);
      *(float4*)(sm+O_P+544+warp*68+cg4)=make_float4(q[0],q[1],q[2],q[3]);
    }
  }
}
DEV void stage2(float* sm,int tid){
  if(tid<64){
    float s=0.f,q=0.f;
#pragma unroll
    for(int g=0;g<8;g++){ s+=sm[O_P+g*68+tid]; q+=sm[O_P+544+g*68+tid]; }
    float m=s*(1.f/64.f), v=q*(1.f/64.f)-m*m;
    sm[O_MNR+tid]=m; sm[O_MNR+64+tid]=rsqrtf(v+1e-5f);
  }
}
DEV void normA(float* A,const float* sm,int li,int rg4,int cg4){
  float4 m4=*(const float4*)(sm+O_MNR+cg4), r4=*(const float4*)(sm+O_MNR+64+cg4);
#pragma unroll
  for(int r=0;r<4;r++){
    int fr=rg4+r;
    float g=sm[LNGo+li*64+fr], bb=sm[LNBo+li*64+fr];
    float4 v=*(float4*)(A+fr*68+cg4);
    v.x=(v.x-m4.x)*r4.x*g+bb; v.y=(v.y-m4.y)*r4.y*g+bb;
    v.z=(v.z-m4.z)*r4.z*g+bb; v.w=(v.w-m4.w)*r4.w*g+bb;
    *(float4*)(A+fr*68+cg4)=v;
  }
}
DEV void cpT(float* dst,const float* __restrict__ src,int R,int K,int ks,int tid){
  for(int i=tid;i<R*K;i+=NT){ int r=i/K,k=i-r*K; dst[k*ks+r]=src[i]; }
}
} // namespace

__global__ void __launch_bounds__(NT,1)
sysid_kernel(const float* __restrict__ obs,
             const float* __restrict__ sysA,const float* __restrict__ sysB_,const float* __restrict__ sysC,
             const float* __restrict__ rWi,const float* __restrict__ rWh,
             const float* __restrict__ rbi,const float* __restrict__ rbh,
             const float* __restrict__ cWi,const float* __restrict__ cWh,
             const float* __restrict__ cbi,const float* __restrict__ cbh,
             const float* __restrict__ mW0,const float* __restrict__ mb0,
             const float* __restrict__ mW1,const float* __restrict__ mb1,
             const float* __restrict__ pW0,const float* __restrict__ pb0,
             const float* __restrict__ lg,const float* __restrict__ lb,
             const float* __restrict__ pW,const float* __restrict__ pb,
             const float* __restrict__ wo,const float* __restrict__ wob,
             float* __restrict__ out)
{
  extern __shared__ float sm[];
  const int tid=threadIdx.x, lane=tid&31, warp=tid>>5;
  const int cg4=(lane&15)*4, rg4=(warp*2+(lane>>4))*4;
  const int b0=blockIdx.x*NBT;
  const int oc=tid>>3, oo=tid&7;
  float* A0=sm+O_A0; float* A1=sm+O_A1;
  float* Hr=sm+O_U+32*68;     // rollout H

  // ================= encoder weights + init =================
  cpT(sm+E_W,rWh,192,64,WS,tid);          // image rows 0-63 = Wh
  cpT(sm+E_W+64*WS,rWi,192,8,WS,tid);     // rows 64-71 = Wi
  for(int i=tid;i<64;i+=NT){
    sm[E_B+i]=rbi[i]+rbh[i]; sm[E_B+64+i]=rbi[64+i]+rbh[64+i];
    sm[E_B+128+i]=rbi[128+i]; sm[E_B+192+i]=rbh[128+i];
  }
  for(int i=tid;i<64*68;i+=NT) sm[i]=0.f;                 // buf0 H = 0
  sm[(64+oo)*68+oc]=obs[(size_t)(b0+oc)*1600+oo];         // buf0 X = obs0
  sm[(64+oo)*68+oc+32]=obs[(size_t)(b0+oc+32)*1600+oo];
  __syncthreads();

  // ================= encoder GRU: 200 steps, 1 barrier each =================
#pragma unroll 1
  for(int t=0;t<200;t++){
    float* cur=sm+(t&1)*HXSZ;
    float* nxt=sm+((t+1)&1)*HXSZ;
    int tn=(t<199)?t+1:t;
    float p0=obs[(size_t)(b0+oc)*1600+tn*8+oo];
    float p1=obs[(size_t)(b0+oc+32)*1600+tn*8+oo];
    float2 aR[4][2],aZ[4][2],aI[4][2],aH[4][2];
    z2(aR);z2(aZ);z2(aI);z2(aH);
    gemm3<64>(aR,aZ,aH,sm+E_W,cur,rg4,cg4);
    gemm3<8>(aR,aZ,aI,sm+E_W+64*WS,cur+64*68,rg4,cg4);
    float4 hn[4]; gru_post(sm,E_B,cur,rg4,cg4,aR,aZ,aI,aH,hn);
#pragma unroll
    for(int r=0;r<4;r++) *(float4*)(nxt+(rg4+r)*68+cg4)=hn[r];
    nxt[(64+oo)*68+oc]=p0; nxt[(64+oo)*68+oc+32]=p1;
    __syncthreads();
  }
  // hT in buf0 rows 0-63

  // ================= init MLP =================
  for(int i=tid;i<64*72;i+=NT){ int r=i/72,k=i-r*72; sm[O_W+k*68+r]=mW0[i]; }
  sm[(64+oo)*68+oc]=obs[(size_t)(b0+oc)*1600+oo];
  sm[(64+oo)*68+oc+32]=obs[(size_t)(b0+oc+32)*1600+oo];
  __syncthreads();
  {
    float2 a[4][2]; z2(a);
    gemm1<64>(a,sm+O_W,sm,rg4,cg4);
    gemm1<8>(a,sm+O_W+64*68,sm+64*68,rg4,cg4);
#pragma unroll
    for(int r=0;r<4;r++){
      float bb=__ldg(mb0+rg4+r);
      float4 v=make_float4(tanh_f(gat(a,0,r)+bb),tanh_f(gat(a,1,r)+bb),
                           tanh_f(gat(a,2,r)+bb),tanh_f(gat(a,3,r)+bb));
      *(float4*)(A0+(rg4+r)*68+cg4)=v;
    }
  }
  __syncthreads();
  {
    int col=tid&63, rq=tid>>6;
#pragma unroll
    for(int i=0;i<4;i++){
      int r=rq*4+i;
      float acc=__ldg(mb1+r);
      for(int k=0;k<64;k++) acc=fmaf(A0[k*68+col],__ldg(mW1+r*64+k),acc);
      sm[O_U+r*68+col]=acc;
      out[OFF_ST+(size_t)(b0+col)*3200+r]=acc;
    }
    for(int i=tid;i<64*68;i+=NT) Hr[i]=0.f;
    sm[O_U+(16+oo)*68+oc]=obs[(size_t)(b0+oc)*1600+8+oo];
    sm[O_U+(16+oo)*68+oc+32]=obs[(size_t)(b0+oc+32)*1600+8+oo];
  }
  // rollout weights (same phase: gemm reads of O_W finished at previous barrier)
  cpT(sm+C_W,cWi,192,32,WS,tid);          // image rows 0-31 = Wi
  cpT(sm+C_W+32*WS,cWh,192,64,WS,tid);    // rows 32-95 = Wh
  for(int i=tid;i<64;i+=NT){
    sm[C_B+i]=cbi[i]+cbh[i]; sm[C_B+64+i]=cbi[64+i]+cbh[64+i];
    sm[C_B+128+i]=cbi[128+i]; sm[C_B+192+i]=cbh[128+i];
  }
  for(int i=tid;i<64*80;i+=NT){ int r=i/80,k=i-r*80;
    if(k<64) sm[W0H+k*68+r]=pW0[i]; else sm[W0XE+(k-64)*68+r]=pW0[i]; }
  for(int i=tid;i<64;i+=NT) sm[W0B+i]=pb0[i];
  for(int i=tid;i<12288;i+=NT){ int li=i>>12,rem=i&4095,r=rem>>6,k=rem&63;
    sm[PWt+li*4352+k*68+r]=pW[i]; }
  for(int i=tid;i<192;i+=NT){ sm[PBo+i]=pb[i]; sm[LNGo+i]=lg[i]; sm[LNBo+i]=lb[i]; }
  for(int i=tid;i<256;i+=NT){ sm[WOo+i]=wo[i]; sm[AMo+i]=sysA[i]; }
  if(tid<4) sm[WOBo+tid]=wob[tid];
  for(int i=tid;i<64;i+=NT) sm[BMo+i]=sysB_[i];
  for(int i=tid;i<128;i+=NT) sm[CMs+i]=sysC[i];
  __syncthreads();

  // ================= rollout: 199 steps =================
  const int s1row=tid>>5, s1c=(lane)*2;
#pragma unroll 1
  for(int t=1;t<200;t++){
    int tn=(t<199)?t+1:t;
    float p0=obs[(size_t)(b0+oc)*1600+tn*8+oo];
    float p1=obs[(size_t)(b0+oc+32)*1600+tn*8+oo];

    // S1: oh = C@s ; e = x - oh (all 256 threads, 2 cols each)
    {
      float2 o=make_float2(0.f,0.f);
#pragma unroll
      for(int k=0;k<16;k++){
        float cw=sm[CMs+s1row*16+k];
        float2 sv=*(const float2*)(sm+O_U+k*68+s1c);
        o.x=fmaf(cw,sv.x,o.x); o.y=fmaf(cw,sv.y,o.y);
      }
      float2 xv=*(const float2*)(sm+O_U+(16+s1row)*68+s1c);
      *(float2*)(sm+O_U+(24+s1row)*68+s1c)=make_float2(xv.x-o.x,xv.y-o.y);
      *(float2*)(sm+O_OHS+s1row*68+s1c)=o;
    }
    __syncthreads();
    // warps 2,3: coalesced obs_hat[t-1] store (32B contiguous per column)
    if(tid>=64&&tid<128){
      int col=tid-64;
      float v[8];
#pragma unroll
      for(int r=0;r<8;r++) v[r]=sm[O_OHS+r*68+col];
      float* dst=out+(size_t)(b0+col)*1600+(size_t)(t-1)*8;
      *(float4*)dst=make_float4(v[0],v[1],v[2],v[3]);
      *(float4*)(dst+4)=make_float4(v[4],v[5],v[6],v[7]);
    }

    // S2: GRU on [U(32); H(64)]
    {
      float2 aR[4][2],aZ[4][2],aI[4][2],aH[4][2];
      z2(aR);z2(aZ);z2(aI);z2(aH);
      gemm3<32>(aR,aZ,aI,sm+C_W,sm+O_U,rg4,cg4);
      gemm3<64>(aR,aZ,aH,sm+C_W+32*WS,Hr,rg4,cg4);
      float4 hn[4]; gru_post(sm,C_B,Hr,rg4,cg4,aR,aZ,aI,aH,hn);
      __syncthreads();
#pragma unroll
      for(int r=0;r<4;r++) *(float4*)(Hr+(rg4+r)*68+cg4)=hn[r];
    }
    __syncthreads();

    // S3: W0 ([H;x,e]) -> relu -> LN0
    {
      float2 a[4][2]; z2(a);
      gemm1<64>(a,sm+W0H,Hr,rg4,cg4);
      gemm1<16>(a,sm+W0XE,sm+O_U+16*68,rg4,cg4);
      epi(a,sm+W0B,A0,sm,rg4,cg4,warp,lane,true);
    }
    __syncthreads();
    stage2(sm,tid);
    __syncthreads();
    normA(A0,sm,0,rg4,cg4);
    __syncthreads();

    // S4: 3 x (linear -> relu [-> LN])
    float* cur=A0; float* nxt=A1;
#pragma unroll 1
    for(int li=0;li<3;li++){
      float2 a[4][2]; z2(a);
      gemm1<64>(a,sm+PWt+li*4352,cur,rg4,cg4);
      epi(a,sm+PBo+li*64,nxt,sm,rg4,cg4,warp,lane,li<2);
      __syncthreads();
      if(li<2){ stage2(sm,tid); __syncthreads(); normA(nxt,sm,li+1,rg4,cg4); __syncthreads(); }
      float* tp=cur; cur=nxt; nxt=tp;
    }

    // S5: cmd -> O_CMD (staged)
    {
      int col=tid&63, r=tid>>6;
      float acc=sm[WOBo+r];
      for(int k=0;k<64;k++) acc=fmaf(cur[k*68+col],sm[WOo+r*64+k],acc);
      sm[O_CMD+r*68+col]=acc;
    }
    __syncthreads();

    // S6: ns = s@A.T + cmd@B.T, mask, advance
    {
      int col=tid&63, rq=tid>>6;
      float ns[4];
#pragma unroll
      for(int i=0;i<4;i++){
        int r=rq*4+i; float a=0.f;
#pragma unroll
        for(int k=0;k<16;k++) a=fmaf(sm[AMo+r*16+k],sm[O_U+k*68+col],a);
#pragma unroll
        for(int k=0;k<4;k++) a=fmaf(sm[BMo+r*4+k],sm[O_CMD+k*68+col],a);
        ns[i]=(a>-100.f&&a<100.f)?a:0.f;
      }
      __syncthreads();
#pragma unroll
      for(int i=0;i<4;i++) sm[O_U+(rq*4+i)*68+col]=ns[i];
      sm[O_U+(16+oo)*68+oc]=p0; sm[O_U+(16+oo)*68+oc+32]=p1;
    }
    __syncthreads();
    // warps 0,1: coalesced states[t] (64B) + commands[t-1] (16B) per column
    if(tid<64){
      int col=tid;
      float* ds=out+OFF_ST+(size_t)(b0+col)*3200+(size_t)t*16;
#pragma unroll
      for(int q=0;q<4;q++){
        float4 v=make_float4(sm[O_U+(q*4+0)*68+col],sm[O_U+(q*4+1)*68+col],
                             sm[O_U+(q*4+2)*68+col],sm[O_U+(q*4+3)*68+col]);
        *(float4*)(ds+q*4)=v;
      }
      float4 cv=make_float4(sm[O_CMD+0*68+col],sm[O_CMD+1*68+col],
                            sm[O_CMD+2*68+col],sm[O_CMD+3*68+col]);
      *(float4*)(out+OFF_CMD+(size_t)(b0+col)*796+(size_t)(t-1)*4)=cv;
    }
  }

  // tail: obs_hat[199] = states[199]@C.T
  {
    float2 o=make_float2(0.f,0.f);
#pragma unroll
    for(int k=0;k<16;k++){
      float cw=sm[CMs+s1row*16+k];
      float2 sv=*(const float2*)(sm+O_U+k*68+s1c);
      o.x=fmaf(cw,sv.x,o.x); o.y=fmaf(cw,sv.y,o.y);
    }
    out[(size_t)(b0+s1c)*1600+1592+s1row]=o.x;
    out[(size_t)(b0+s1c+1)*1600+1592+s1row]=o.y;
  }
}

extern "C" void kernel_launch(void* const* d_in, const int* in_sizes, int n_in,
                              void* d_out, int out_size) {
  (void)in_sizes;(void)n_in;(void)out_size;
  cudaFuncSetAttribute(sysid_kernel,cudaFuncAttributeMaxDynamicSharedMemorySize,(int)SMEMB);
  sysid_kernel<<<NB/NBT,NT,SMEMB>>>(
    (const float*)d_in[0],(const float*)d_in[1],(const float*)d_in[2],(const float*)d_in[3],
    (const float*)d_in[4],(const float*)d_in[5],(const float*)d_in[6],(const float*)d_in[7],
    (const float*)d_in[8],(const float*)d_in[9],(const float*)d_in[10],(const float*)d_in[11],
    (const float*)d_in[12],(const float*)d_in[13],(const float*)d_in[14],(const float*)d_in[15],
    (const float*)d_in[16],(const float*)d_in[17],(const float*)d_in[18],(const float*)d_in[19],
    (const float*)d_in[20],(const float*)d_in[21],(const float*)d_in[22],(const float*)d_in[23],
    (float*)d_out);
}